// round 1
// baseline (speedup 1.0000x reference)
#include <cuda_runtime.h>

// out[b, H-1-h, w] = exp(EPS)*o[0] + sum_{d=1}^{D-1} (prod_{k<d}(1-o[k])) * o[d]
// o = clip(v, EPS, 1-EPS).  Pure streaming reduction along depth; HBM-bound.

#define EPSF      1e-5f
#define ONE_MEPS  (1.0f - 1e-5f)
#define EXP_EPS   1.0000100000500002f   // expf(1e-5f)

static __device__ __forceinline__ float clipv(float v) {
    return fminf(fmaxf(v, EPSF), ONE_MEPS);
}

__global__ void __launch_bounds__(256)
eff_loss_kernel(const float* __restrict__ vox, float* __restrict__ out) {
    constexpr int B = 16, D = 128, H = 128, W = 128;
    constexpr int W4 = W / 4;               // 32 float4 per row
    constexpr int DSTRIDE = H * W4;         // float4 stride between depth slices (4096)

    int idx = blockIdx.x * blockDim.x + threadIdx.x;   // over B*H*W4 = 65536
    if (idx >= B * H * W4) return;

    int w4 = idx % W4;
    int h  = (idx / W4) % H;
    int b  =  idx / (W4 * H);

    const float4* p = reinterpret_cast<const float4*>(vox)
                    + (size_t)b * D * DSTRIDE + (size_t)h * W4 + w4;

    // d = 0
    float4 v0 = p[0];
    float ox = clipv(v0.x), oy = clipv(v0.y), oz = clipv(v0.z), ow = clipv(v0.w);
    float ax = EXP_EPS * ox, ay = EXP_EPS * oy, az = EXP_EPS * oz, aw = EXP_EPS * ow;
    float Tx = 1.0f, Ty = 1.0f, Tz = 1.0f, Tw = 1.0f;

    #pragma unroll 8
    for (int d = 1; d < D; ++d) {
        float4 c = p[(size_t)d * DSTRIDE];
        float cx = clipv(c.x), cy = clipv(c.y), cz = clipv(c.z), cw = clipv(c.w);
        Tx *= (1.0f - ox);  Ty *= (1.0f - oy);
        Tz *= (1.0f - oz);  Tw *= (1.0f - ow);
        ax = fmaf(Tx, cx, ax);  ay = fmaf(Ty, cy, ay);
        az = fmaf(Tz, cz, az);  aw = fmaf(Tw, cw, aw);
        ox = cx; oy = cy; oz = cz; ow = cw;
    }

    // vertical flip: output row H-1-h
    float4 r = make_float4(ax, ay, az, aw);
    reinterpret_cast<float4*>(out)[(size_t)b * H * W4 + (size_t)(H - 1 - h) * W4 + w4] = r;
}

extern "C" void kernel_launch(void* const* d_in, const int* in_sizes, int n_in,
                              void* d_out, int out_size) {
    const float* vox = (const float*)d_in[0];
    float* out = (float*)d_out;
    constexpr int TOTAL = 16 * 128 * 32;   // B*H*W4 threads
    eff_loss_kernel<<<TOTAL / 256, 256>>>(vox, out);
}

// round 2
// speedup vs baseline: 1.3384x; 1.3384x over previous
#include <cuda_runtime.h>

// out[b, H-1-h, w] = exp(EPS)*o[0] + sum_{d=1}^{D-1} (prod_{k<d}(1-o[k])) * o[d]
// o = clip(v, EPS, 1-EPS).
//
// Depth-split scan: D=128 split into NSEG=4 segments of 32. Each thread computes
// a partial pair (A_s, T_s) for one segment of one float4-ray; pairs compose
// associatively A = A_lo + T_lo*A_hi, T = T_lo*T_hi via 2 warp-shuffle steps.
// Warp layout: 8 consecutive float4-rays x 4 segments (lane = seg*8 + ray).

#define EPSF      1e-5f
#define ONE_MEPS  (1.0f - 1e-5f)
#define EXP_EPS   1.0000100000500002f   // expf(1e-5f)

static __device__ __forceinline__ float clipv(float v) {
    return fminf(fmaxf(v, EPSF), ONE_MEPS);
}

__global__ void __launch_bounds__(256)
eff_loss_kernel(const float* __restrict__ vox, float* __restrict__ out) {
    constexpr int B = 16, D = 128, H = 128, W = 128;
    constexpr int W4 = W / 4;                 // 32 float4 per row
    constexpr int DSTRIDE = H * W4;           // float4 stride per depth slice (4096)
    constexpr int NSEG = 4;
    constexpr int SEGD = D / NSEG;            // 32 slices per segment

    int tid  = blockIdx.x * blockDim.x + threadIdx.x;  // 262144 threads
    int lane = tid & 31;
    int seg  = lane >> 3;                      // 0..3
    int ray  = (tid >> 5) * 8 + (lane & 7);    // float4-ray id, 0..65535

    int w4 = ray & (W4 - 1);
    int h  = (ray >> 5) & (H - 1);
    int b  =  ray >> 12;

    const float4* p = reinterpret_cast<const float4*>(vox)
                    + (size_t)b * D * DSTRIDE
                    + (size_t)(seg * SEGD) * DSTRIDE
                    + (size_t)h * W4 + w4;

    // first slice of segment: weight exp(EPS) only for the global d=0 term
    float w0 = (seg == 0) ? EXP_EPS : 1.0f;
    float4 v0 = p[0];
    float ox = clipv(v0.x), oy = clipv(v0.y), oz = clipv(v0.z), ow = clipv(v0.w);
    float ax = w0 * ox, ay = w0 * oy, az = w0 * oz, aw = w0 * ow;
    float Tx = 1.0f, Ty = 1.0f, Tz = 1.0f, Tw = 1.0f;

    #pragma unroll 8
    for (int d = 1; d < SEGD; ++d) {
        float4 c = p[(size_t)d * DSTRIDE];
        float cx = clipv(c.x), cy = clipv(c.y), cz = clipv(c.z), cw = clipv(c.w);
        Tx *= (1.0f - ox);  Ty *= (1.0f - oy);
        Tz *= (1.0f - oz);  Tw *= (1.0f - ow);
        ax = fmaf(Tx, cx, ax);  ay = fmaf(Ty, cy, ay);
        az = fmaf(Tz, cz, az);  aw = fmaf(Tw, cw, aw);
        ox = cx; oy = cy; oz = cz; ow = cw;
    }
    // close the segment transmittance: include last element
    Tx *= (1.0f - ox);  Ty *= (1.0f - oy);
    Tz *= (1.0f - oz);  Tw *= (1.0f - ow);

    const unsigned m = 0xffffffffu;

    // combine (0,1) and (2,3): stride 8
    {
        float bax = __shfl_down_sync(m, ax, 8), bay = __shfl_down_sync(m, ay, 8);
        float baz = __shfl_down_sync(m, az, 8), baw = __shfl_down_sync(m, aw, 8);
        float btx = __shfl_down_sync(m, Tx, 8), bty = __shfl_down_sync(m, Ty, 8);
        float btz = __shfl_down_sync(m, Tz, 8), btw = __shfl_down_sync(m, Tw, 8);
        ax = fmaf(Tx, bax, ax);  ay = fmaf(Ty, bay, ay);
        az = fmaf(Tz, baz, az);  aw = fmaf(Tw, baw, aw);
        Tx *= btx;  Ty *= bty;  Tz *= btz;  Tw *= btw;
    }
    // combine (01, 23): stride 16
    {
        float bax = __shfl_down_sync(m, ax, 16), bay = __shfl_down_sync(m, ay, 16);
        float baz = __shfl_down_sync(m, az, 16), baw = __shfl_down_sync(m, aw, 16);
        ax = fmaf(Tx, bax, ax);  ay = fmaf(Ty, bay, ay);
        az = fmaf(Tz, baz, az);  aw = fmaf(Tw, baw, aw);
    }

    if (seg == 0) {
        reinterpret_cast<float4*>(out)[(size_t)b * H * W4
                                       + (size_t)(H - 1 - h) * W4 + w4]
            = make_float4(ax, ay, az, aw);
    }
}

extern "C" void kernel_launch(void* const* d_in, const int* in_sizes, int n_in,
                              void* d_out, int out_size) {
    const float* vox = (const float*)d_in[0];
    float* out = (float*)d_out;
    constexpr int TOTAL = 16 * 128 * 32 * 4;   // rays * NSEG
    eff_loss_kernel<<<TOTAL / 256, 256>>>(vox, out);
}